// round 5
// baseline (speedup 1.0000x reference)
#include <cuda_runtime.h>
#include <cuda_bf16.h>

// ALiBi: out[b,h,i,j] = scores[b,h,i,j] + (j - i) * slopes[h]
// B=2, H=16, S=2048. Pure HBM streaming: 512 MiB in + 512 MiB out.
//
// R4: UNROLL=8 (8 independent front-batched LDG.128 per thread -> MLP_eff=8),
// 8 rows per 512-thread block, streaming cache hints, grid=8192.

static constexpr int S = 2048;
static constexpr int H = 16;
static constexpr int THREADS = 512;
static constexpr int LANES_PER_ROW = 64;      // threads covering one row
static constexpr int ROWS_PER_BLOCK = 8;      // 512 / 64
static constexpr int UNROLL = 8;              // float4s per thread: 64*8*4 = 2048 floats = one row

__global__ void __launch_bounds__(THREADS, 2)
alibi_kernel(const float* __restrict__ scores,
             const float* __restrict__ slopes,
             float* __restrict__ out)
{
    const int tid  = threadIdx.x;
    const int lane = tid & (LANES_PER_ROW - 1);       // 0..63
    const int rib  = tid >> 6;                        // row within block, 0..7

    const unsigned row = blockIdx.x * ROWS_PER_BLOCK + rib;
    const int i = row & (S - 1);
    const int h = (row >> 11) & (H - 1);
    const float slope = __ldg(&slopes[h]);

    // This thread's 8 float4s: columns j0 + k*256 floats (k=0..7), same row.
    const int j0 = lane * 4;
    const size_t base = (size_t)row * S + j0;

    const float4* __restrict__ src = reinterpret_cast<const float4*>(scores + base);
    float4*       __restrict__ dst = reinterpret_cast<float4*>(out + base);

    // Front-batch all 8 independent loads -> 8 outstanding DRAM requests
    float4 v[UNROLL];
#pragma unroll
    for (int k = 0; k < UNROLL; k++)
        v[k] = __ldcs(src + k * LANES_PER_ROW);       // stride 64 float4 = 256 floats

    // bias = (j - i) * slope
#pragma unroll
    for (int k = 0; k < UNROLL; k++) {
        const float d0 = (float)(j0 + k * (LANES_PER_ROW * 4) - i);
        v[k].x = fmaf(d0,        slope, v[k].x);
        v[k].y = fmaf(d0 + 1.0f, slope, v[k].y);
        v[k].z = fmaf(d0 + 2.0f, slope, v[k].z);
        v[k].w = fmaf(d0 + 3.0f, slope, v[k].w);
    }

#pragma unroll
    for (int k = 0; k < UNROLL; k++)
        __stcs(dst + k * LANES_PER_ROW, v[k]);
}

extern "C" void kernel_launch(void* const* d_in, const int* in_sizes, int n_in,
                              void* d_out, int out_size)
{
    const float* scores = (const float*)d_in[0];
    const float* slopes = (const float*)d_in[1];
    float* out = (float*)d_out;

    const long long total = (long long)out_size;          // B*H*S*S
    const int rows = (int)(total / S);                    // 65536
    const int blocks = rows / ROWS_PER_BLOCK;             // 8192

    alibi_kernel<<<blocks, THREADS>>>(scores, slopes, out);
}